// round 10
// baseline (speedup 1.0000x reference)
#include <cuda_runtime.h>
#include <cuda_fp16.h>
#include <math.h>
#include <stdint.h>

#define NQ 1024
#define NS 256
#define E  256
#define H1 256
#define H2 128
#define H3 64
#define TM 128          // query rows per CTA

// ---------------- warp-MMA helpers (plain sm_80+ PTX) -----------------------
__device__ __forceinline__ uint32_t smem_to_u32(const void* p) {
    uint32_t a;
    asm("{ .reg .u64 t; cvta.to.shared.u64 t, %1; cvt.u32.u64 %0, t; }" : "=r"(a) : "l"(p));
    return a;
}
__device__ __forceinline__ void ldsm4(uint32_t* r, uint32_t addr) {
    asm volatile("ldmatrix.sync.aligned.m8n8.x4.shared.b16 {%0,%1,%2,%3}, [%4];"
                 : "=r"(r[0]), "=r"(r[1]), "=r"(r[2]), "=r"(r[3]) : "r"(addr));
}
__device__ __forceinline__ void mma_f16(float* d, const uint32_t* a, const uint32_t* b) {
    asm volatile("mma.sync.aligned.m16n8k16.row.col.f32.f16.f16.f32 "
                 "{%0,%1,%2,%3}, {%4,%5,%6,%7}, {%8,%9}, {%0,%1,%2,%3};"
                 : "+f"(d[0]), "+f"(d[1]), "+f"(d[2]), "+f"(d[3])
                 : "r"(a[0]), "r"(a[1]), "r"(a[2]), "r"(a[3]), "r"(b[0]), "r"(b[1]));
}
// fp16-accumulator variant: D = A*B + C (all f16). C may be zero regs.
__device__ __forceinline__ void mma_f16h(uint32_t* d, const uint32_t* a,
                                         const uint32_t* b, const uint32_t* c) {
    asm volatile("mma.sync.aligned.m16n8k16.row.col.f16.f16.f16.f16 "
                 "{%0,%1}, {%2,%3,%4,%5}, {%6,%7}, {%8,%9};"
                 : "=r"(d[0]), "=r"(d[1])
                 : "r"(a[0]), "r"(a[1]), "r"(a[2]), "r"(a[3]),
                   "r"(b[0]), "r"(b[1]), "r"(c[0]), "r"(c[1]));
}
__device__ __forceinline__ void cp_async16(uint32_t dst_smem, const void* src) {
    asm volatile("cp.async.cg.shared.global [%0], [%1], 16;"
                 :: "r"(dst_smem), "l"(src));
}
#define CP_ASYNC_COMMIT() asm volatile("cp.async.commit_group;" ::: "memory")
#define CP_ASYNC_WAIT0()  asm volatile("cp.async.wait_group 0;" ::: "memory")

__device__ __forceinline__ void split_f16(float x, __half& hi, __half& lo) {
    hi = __float2half_rn(x);
    lo = __float2half_rn(x - __half2float(hi));
}
__device__ __forceinline__ uint32_t pack2h(__half a, __half b) {
    __half2 t; t.x = a; t.y = b;
    return *reinterpret_cast<uint32_t*>(&t);
}
__device__ __forceinline__ uint32_t hadd2_relu(uint32_t a, uint32_t b) {
    __half2 r = __hmax2(__hadd2(*reinterpret_cast<__half2*>(&a),
                                *reinterpret_cast<__half2*>(&b)),
                        __half2(__half(0.0f), __half(0.0f)));
    return *reinterpret_cast<uint32_t*>(&r);
}
// promote one f16 D-fragment (2 regs = c0..c3) into 4 f32 accumulators
__device__ __forceinline__ void promote(float* acc4, const uint32_t* h) {
    const float2 lo = __half22float2(*reinterpret_cast<const __half2*>(&h[0]));
    const float2 hi = __half22float2(*reinterpret_cast<const __half2*>(&h[1]));
    acc4[0] += lo.x; acc4[1] += lo.y; acc4[2] += hi.x; acc4[3] += hi.y;
}
__device__ __forceinline__ float frelu(float x) { return fmaxf(x, 0.0f); }

// ---------------- global scratch (static) -----------------------------------
__device__ uint4  g_QpF[16 * 64 * 32];        // [K16][M16][lane] fp16 A-fragments
__device__ float  g_Sp [NS * H1];             // [s][k] (+b1)
__device__ __half g_W1TB_hi[163840];          // [(half*8+c)*256+n]*40+kk (kk<32)
__device__ __half g_W1TB_lo[163840];
__device__ __half g_W2TB[128 * 264];          // [n][264k] fp16, k<256 data
__device__ __half g_W3TB[8704];               // [n*136+k] fp16

// ---------------- main-kernel smem layout (bytes) ----------------------------
#define SM_W2   0         // whole W2^T [128n][264k] fp16 = 67584
#define SM_W3   0         // phase B: W3^T [64n][136k] = 17408 (aliases SM_W2)
#define SM_H2   67584     // h2 fp16 [128m][136k] = 34816 (ends 102400)
#define SM_SP16 102400    // 256 fp16 = 512
#define SM_B2S  102912    // 128 f32
#define SM_B3S  103424    // 64 f32
#define SM_W4S  103680    // 64 f32
#define SM_RED  103936    // 2*128 f32 = 1024
#define SMEM_TOTAL 104960

// ---------------- precompute-kernel smem layout ------------------------------
#define PSM_A  0          // feat fp16 [128m][264k] = 67584
#define PSM_B  67584      // W1 stage: 2 x (hi 10240 + lo 10240) = 40960
#define PB_STRIDE 20480
#define PRE_SMEM_TOTAL 108544

// ---------------------------------------------------------------------------
__global__ void prep_weights_kernel(const float* __restrict__ W1,
                                    const float* __restrict__ W2,
                                    const float* __restrict__ W3)
{
    const int t = blockIdx.x * blockDim.x + threadIdx.x;   // 640*256 = 163840
    if (t < 163840) {
        const int kk = t % 40;
        const int n  = (t / 40) & 255;
        const int c  = (t / (40 * 256)) & 7;
        const int hf = t / (40 * 256 * 8);
        const float w = (kk < 32) ? W1[(hf * 256 + c * 32 + kk) * H1 + n] : 0.0f;
        __half hi, lo; split_f16(w, hi, lo);
        g_W1TB_hi[t] = hi;
        g_W1TB_lo[t] = lo;
    }
    if (t < 128 * 264) {
        const int n = t / 264, k = t % 264;
        const float w = (k < 256) ? W2[k * H2 + n] : 0.0f;
        g_W2TB[t] = __float2half_rn(w);
    }
    if (t < 8704) {
        const int n = t / 136, k = t % 136;
        const float w = (k < 128) ? W3[k * H3 + n] : 0.0f;
        g_W3TB[t] = __float2half_rn(w);
    }
}

// ---------------------------------------------------------------------------
// Precompute via mma (f32 acc, W1 hi+lo): Qp -> g_QpF fragments; Sp -> g_Sp.
// ---------------------------------------------------------------------------
__global__ void __launch_bounds__(256)
precompute_mma_kernel(const float* __restrict__ qf,
                      const float* __restrict__ sf,
                      const float* __restrict__ b1)
{
    extern __shared__ char smem[];
    const uint32_t sb = smem_to_u32(smem);
    const int tid  = threadIdx.x;
    const int lane = tid & 31;
    const int wid  = tid >> 5;
    const int wm   = wid & 3;
    const int wn   = wid >> 2;
    const int mb   = blockIdx.x;       // 0..9
    const int nb   = blockIdx.y;       // 0..1
    const bool isQ = (mb < 8);
    const float* feat = isQ ? (qf + mb * 128 * E) : (sf + (mb - 8) * 128 * E);
    const int hf = isQ ? 0 : 1;

    {
        const int row = tid >> 1, hv = tid & 1;
        const float4* src = reinterpret_cast<const float4*>(feat + row * E);
        uint32_t* dst = reinterpret_cast<uint32_t*>(smem + PSM_A);
        #pragma unroll 8
        for (int j = 0; j < 32; ++j) {
            const float4 v = src[hv * 32 + j];
            const int u = row * 132 + (hv * 32 + j) * 2;
            dst[u]     = pack2h(__float2half_rn(v.x), __float2half_rn(v.y));
            dst[u + 1] = pack2h(__float2half_rn(v.z), __float2half_rn(v.w));
        }
    }
    {
        const char* srcH = (const char*)&g_W1TB_hi[((hf * 8 + 0) * 256 + nb * 128) * 40];
        const char* srcL = (const char*)&g_W1TB_lo[((hf * 8 + 0) * 256 + nb * 128) * 40];
        const uint32_t dstH = sb + PSM_B;
        #pragma unroll
        for (int i = 0; i < 3; ++i) {
            const int t = tid + 256 * i;
            if (t < 640) {
                cp_async16(dstH + t * 16, srcH + t * 16);
                cp_async16(dstH + 10240 + t * 16, srcL + t * 16);
            }
        }
        CP_ASYNC_COMMIT();
    }
    __syncthreads();

    float acc[2][8][4];
    #pragma unroll
    for (int a = 0; a < 2; a++)
        #pragma unroll
        for (int b = 0; b < 8; b++)
            #pragma unroll
            for (int c = 0; c < 4; c++) acc[a][b][c] = 0.0f;

    for (int c = 0; c < 8; ++c) {
        const int st = c & 1;
        CP_ASYNC_WAIT0();
        __syncthreads();
        if (c < 7) {
            const int base = ((hf * 8 + c + 1) * 256 + nb * 128) * 40;
            const char* srcH = (const char*)&g_W1TB_hi[base];
            const char* srcL = (const char*)&g_W1TB_lo[base];
            const uint32_t dstH = sb + PSM_B + (st ^ 1) * PB_STRIDE;
            #pragma unroll
            for (int i = 0; i < 3; ++i) {
                const int t = tid + 256 * i;
                if (t < 640) {
                    cp_async16(dstH + t * 16, srcH + t * 16);
                    cp_async16(dstH + 10240 + t * 16, srcL + t * 16);
                }
            }
            CP_ASYNC_COMMIT();
        }
        const uint32_t bufH = sb + PSM_B + st * PB_STRIDE;
        #pragma unroll
        for (int ks = 0; ks < 2; ++ks) {
            uint32_t afr[2][4];
            #pragma unroll
            for (int tm = 0; tm < 2; ++tm) {
                const int mrow = wm * 32 + tm * 16 + (lane & 7) + 8 * ((lane >> 3) & 1);
                const int kcol = c * 32 + ks * 16 + 8 * (lane >> 4);
                ldsm4(afr[tm], sb + PSM_A + mrow * 528 + kcol * 2);
            }
            #pragma unroll
            for (int tp = 0; tp < 4; ++tp) {
                uint32_t bh[4], bl[4];
                const int nrow = wn * 64 + tp * 16 + (lane & 7) + 8 * (lane >> 4);
                const int kcol = ks * 16 + 8 * ((lane >> 3) & 1);
                const uint32_t baddr = bufH + nrow * 80 + kcol * 2;
                ldsm4(bh, baddr);
                ldsm4(bl, baddr + 10240);
                #pragma unroll
                for (int tm = 0; tm < 2; ++tm) {
                    mma_f16(acc[tm][2*tp    ], afr[tm], &bh[0]);
                    mma_f16(acc[tm][2*tp    ], afr[tm], &bl[0]);
                    mma_f16(acc[tm][2*tp + 1], afr[tm], &bh[2]);
                    mma_f16(acc[tm][2*tp + 1], afr[tm], &bl[2]);
                }
            }
        }
    }

    if (isQ) {
        #pragma unroll
        for (int tm = 0; tm < 2; ++tm)
            #pragma unroll
            for (int tnp = 0; tnp < 4; ++tnp) {
                const int K16 = nb * 8 + wn * 4 + tnp;
                const int M16 = mb * 8 + wm * 2 + tm;
                uint4 v;
                v.x = pack2h(__float2half_rn(acc[tm][2*tnp][0]),
                             __float2half_rn(acc[tm][2*tnp][1]));
                v.y = pack2h(__float2half_rn(acc[tm][2*tnp][2]),
                             __float2half_rn(acc[tm][2*tnp][3]));
                v.z = pack2h(__float2half_rn(acc[tm][2*tnp+1][0]),
                             __float2half_rn(acc[tm][2*tnp+1][1]));
                v.w = pack2h(__float2half_rn(acc[tm][2*tnp+1][2]),
                             __float2half_rn(acc[tm][2*tnp+1][3]));
                g_QpF[(K16 * 64 + M16) * 32 + lane] = v;
            }
    } else {
        const int s0 = (mb - 8) * 128;
        #pragma unroll
        for (int tm = 0; tm < 2; ++tm)
            #pragma unroll
            for (int tn = 0; tn < 8; ++tn) {
                const int n = nb * 128 + wn * 64 + tn * 8 + (lane & 3) * 2;
                const float bb0 = b1[n], bb1 = b1[n + 1];
                #pragma unroll
                for (int rr = 0; rr < 2; ++rr) {
                    const int m = wm * 32 + tm * 16 + rr * 8 + (lane >> 2);
                    g_Sp[(s0 + m) * H1 + n]     = acc[tm][tn][2*rr]     + bb0;
                    g_Sp[(s0 + m) * H1 + n + 1] = acc[tm][tn][2*rr + 1] + bb1;
                }
            }
    }
}

// ---------------------------------------------------------------------------
// Fused MLP. R9 experiment: layers 2/3 mma with fp16 accumulators (K=32
// groups, C=0 seeded), promoted to fp32 per group. Tests rt(f16acc)=rt/2.
// ---------------------------------------------------------------------------
__global__ void __launch_bounds__(256, 2)
relation_mma_kernel(const float* __restrict__ b2,
                    const float* __restrict__ b3,
                    const float* __restrict__ W4,
                    const float* __restrict__ b4,
                    float* __restrict__ out)
{
    extern __shared__ char smem[];
    const uint32_t sb = smem_to_u32(smem);
    const int tid  = threadIdx.x;
    const int lane = tid & 31;
    const int wid  = tid >> 5;
    const int wm   = wid & 3;
    const int wn   = wid >> 2;
    const int s_idx = blockIdx.x;
    const int q0    = blockIdx.y * TM;
    const int M16b  = blockIdx.y * 8 + wm * 2;

    float* b2s = (float*)(smem + SM_B2S);
    float* b3s = (float*)(smem + SM_B3S);
    float* W4s = (float*)(smem + SM_W4S);
    float* red = (float*)(smem + SM_RED);
    __half* sp16 = (__half*)(smem + SM_SP16);

    sp16[tid] = __float2half_rn(g_Sp[s_idx * H1 + tid]);
    if (tid < H2) b2s[tid] = b2[tid];
    if (tid < H3) { b3s[tid] = b3[tid]; W4s[tid] = W4[tid]; }

    // ---- prologue: cp.async the WHOLE W2 (67584 B = 4224 x 16B) ----
    {
        const char* src = (const char*)g_W2TB;
        #pragma unroll
        for (int i = 0; i < 17; ++i) {
            const int t = tid + 256 * i;
            if (t < 4224) cp_async16(sb + SM_W2 + t * 16, src + t * 16);
        }
        CP_ASYNC_COMMIT();
    }
    uint4 aq[2][2];
    #pragma unroll
    for (int tm = 0; tm < 2; ++tm)
        #pragma unroll
        for (int ks = 0; ks < 2; ++ks)
            aq[tm][ks] = g_QpF[(ks * 64 + M16b + tm) * 32 + lane];

    float acc[2][8][4];
    #pragma unroll
    for (int a = 0; a < 2; a++)
        #pragma unroll
        for (int b = 0; b < 8; b++)
            #pragma unroll
            for (int c = 0; c < 4; c++) acc[a][b][c] = 0.0f;

    const uint32_t zz[2] = {0u, 0u};

    CP_ASYNC_WAIT0();
    __syncthreads();   // W2 + sp16 + biases visible; only barrier before loop

    // ============ layer2 mainloop: 8 chunks of k=32, barrier-free ===========
    #pragma unroll
    for (int c = 0; c < 8; ++c) {
        uint32_t af[2][2][4];
        #pragma unroll
        for (int ks = 0; ks < 2; ++ks) {
            const uint32_t spA = *(const uint32_t*)(smem + SM_SP16 + c * 64 + ks * 32 + (lane & 3) * 4);
            const uint32_t spB = *(const uint32_t*)(smem + SM_SP16 + c * 64 + ks * 32 + (lane & 3) * 4 + 16);
            #pragma unroll
            for (int tm = 0; tm < 2; ++tm) {
                af[tm][ks][0] = hadd2_relu(aq[tm][ks].x, spA);
                af[tm][ks][1] = hadd2_relu(aq[tm][ks].y, spA);
                af[tm][ks][2] = hadd2_relu(aq[tm][ks].z, spB);
                af[tm][ks][3] = hadd2_relu(aq[tm][ks].w, spB);
            }
        }
        if (c < 7) {
            #pragma unroll
            for (int tm = 0; tm < 2; ++tm)
                #pragma unroll
                for (int ks = 0; ks < 2; ++ks)
                    aq[tm][ks] = g_QpF[(((c + 1) * 2 + ks) * 64 + M16b + tm) * 32 + lane];
        }
        // mma phase: fp16 acc over K=32, then promote to fp32
        #pragma unroll
        for (int tp = 0; tp < 4; ++tp) {
            uint32_t hacc[2][2][2];   // [tm][nhalf][reg]
            #pragma unroll
            for (int ks = 0; ks < 2; ++ks) {
                uint32_t bh[4];
                const int nrow = wn * 64 + tp * 16 + (lane & 7) + 8 * (lane >> 4);
                const int kcol = c * 32 + ks * 16 + 8 * ((lane >> 3) & 1);
                ldsm4(bh, sb + SM_W2 + nrow * 528 + kcol * 2);
                #pragma unroll
                for (int tm = 0; tm < 2; ++tm) {
                    mma_f16h(hacc[tm][0], af[tm][ks], &bh[0], ks ? hacc[tm][0] : zz);
                    mma_f16h(hacc[tm][1], af[tm][ks], &bh[2], ks ? hacc[tm][1] : zz);
                }
            }
            #pragma unroll
            for (int tm = 0; tm < 2; ++tm) {
                promote(acc[tm][2*tp    ], hacc[tm][0]);
                promote(acc[tm][2*tp + 1], hacc[tm][1]);
            }
        }
    }
    __syncthreads();   // all W2 reads done CTA-wide; W2 region reusable

    // stage W3^T into W2's region via cp.async (overlaps epilogue below)
    {
        const char* srcH = (const char*)g_W3TB;
        #pragma unroll
        for (int i = 0; i < 5; ++i) {
            const int t = tid + 256 * i;
            if (t < 1088) cp_async16(sb + SM_W3 + t * 16, srcH + t * 16);
        }
        CP_ASYNC_COMMIT();
    }
    // layer2 epilogue: bias+relu -> fp16 -> h2[m][k]
    {
        uint32_t* hh = reinterpret_cast<uint32_t*>(smem + SM_H2);
        #pragma unroll
        for (int tm = 0; tm < 2; ++tm) {
            #pragma unroll
            for (int tn = 0; tn < 8; ++tn) {
                const int n = wn * 64 + tn * 8 + (lane & 3) * 2;
                const int m = wm * 32 + tm * 16 + (lane >> 2);
                const float bn0 = b2s[n], bn1 = b2s[n + 1];
                #pragma unroll
                for (int rr = 0; rr < 2; ++rr) {
                    const float x0 = frelu(acc[tm][tn][2*rr    ] + bn0);
                    const float x1 = frelu(acc[tm][tn][2*rr + 1] + bn1);
                    hh[(m + 8*rr) * 68 + (n >> 1)] =
                        pack2h(__float2half_rn(x0), __float2half_rn(x1));
                }
            }
        }
    }
    CP_ASYNC_WAIT0();
    __syncthreads();

    // ========== layer3: h2[128x128] @ W3[128x64], fp16 acc (K=32) ===========
    float acc3[2][4][4];
    #pragma unroll
    for (int a = 0; a < 2; a++)
        #pragma unroll
        for (int b = 0; b < 4; b++)
            #pragma unroll
            for (int c = 0; c < 4; c++) acc3[a][b][c] = 0.0f;

    #pragma unroll
    for (int k2 = 0; k2 < 4; ++k2) {
        uint32_t afr[2][2][4];   // [ksi][tm]
        #pragma unroll
        for (int ksi = 0; ksi < 2; ++ksi)
            #pragma unroll
            for (int tm = 0; tm < 2; ++tm) {
                const int mrow = wm * 32 + tm * 16 + (lane & 7) + 8 * ((lane >> 3) & 1);
                const int kcol = (k2 * 2 + ksi) * 16 + 8 * (lane >> 4);
                ldsm4(afr[ksi][tm], sb + SM_H2 + mrow * 272 + kcol * 2);
            }
        #pragma unroll
        for (int tp = 0; tp < 2; ++tp) {
            uint32_t hacc[2][2][2];
            #pragma unroll
            for (int ksi = 0; ksi < 2; ++ksi) {
                uint32_t bh[4];
                const int nrow = wn * 32 + tp * 16 + (lane & 7) + 8 * (lane >> 4);
                const int kcol = (k2 * 2 + ksi) * 16 + 8 * ((lane >> 3) & 1);
                ldsm4(bh, sb + SM_W3 + nrow * 272 + kcol * 2);
                #pragma unroll
                for (int tm = 0; tm < 2; ++tm) {
                    mma_f16h(hacc[tm][0], afr[ksi][tm], &bh[0], ksi ? hacc[tm][0] : zz);
                    mma_f16h(hacc[tm][1], afr[ksi][tm], &bh[2], ksi ? hacc[tm][1] : zz);
                }
            }
            #pragma unroll
            for (int tm = 0; tm < 2; ++tm) {
                promote(acc3[tm][2*tp    ], hacc[tm][0]);
                promote(acc3[tm][2*tp + 1], hacc[tm][1]);
            }
        }
    }

    // ============== layer3 epilogue + layer4 (registers + shfl) =============
    float part[4] = {0.0f, 0.0f, 0.0f, 0.0f};
    #pragma unroll
    for (int tn = 0; tn < 4; ++tn) {
        const int n = wn * 32 + tn * 8 + (lane & 3) * 2;
        const float bn0 = b3s[n], bn1 = b3s[n + 1];
        const float w0 = W4s[n],  w1 = W4s[n + 1];
        #pragma unroll
        for (int tm = 0; tm < 2; ++tm) {
            #pragma unroll
            for (int rr = 0; rr < 2; ++rr) {
                part[tm*2 + rr] += frelu(acc3[tm][tn][2*rr    ] + bn0) * w0
                                 + frelu(acc3[tm][tn][2*rr + 1] + bn1) * w1;
            }
        }
    }
    #pragma unroll
    for (int i = 0; i < 4; ++i) {
        part[i] += __shfl_xor_sync(0xffffffffu, part[i], 1);
        part[i] += __shfl_xor_sync(0xffffffffu, part[i], 2);
    }
    if ((lane & 3) == 0) {
        #pragma unroll
        for (int tm = 0; tm < 2; ++tm)
            #pragma unroll
            for (int rr = 0; rr < 2; ++rr) {
                const int m = wm * 32 + tm * 16 + rr * 8 + (lane >> 2);
                red[wn * 128 + m] = part[tm*2 + rr];
            }
    }
    __syncthreads();
    if (tid < 128) {
        const float v = red[tid] + red[128 + tid] + b4[0];
        out[(q0 + tid) * NS + s_idx] = 1.0f / (1.0f + expf(-v));
    }
}

// ---------------------------------------------------------------------------
extern "C" void kernel_launch(void* const* d_in, const int* in_sizes, int n_in,
                              void* d_out, int out_size)
{
    const float* qf = (const float*)d_in[0];
    const float* sf = (const float*)d_in[1];
    // d_in[2] = support_y (unused)
    const float* W1 = (const float*)d_in[3];
    const float* b1 = (const float*)d_in[4];
    const float* W2 = (const float*)d_in[5];
    const float* b2 = (const float*)d_in[6];
    const float* W3 = (const float*)d_in[7];
    const float* b3 = (const float*)d_in[8];
    const float* W4 = (const float*)d_in[9];
    const float* b4 = (const float*)d_in[10];
    float* out = (float*)d_out;

    cudaFuncSetAttribute(relation_mma_kernel,
                         cudaFuncAttributeMaxDynamicSharedMemorySize, SMEM_TOTAL);
    cudaFuncSetAttribute(precompute_mma_kernel,
                         cudaFuncAttributeMaxDynamicSharedMemorySize, PRE_SMEM_TOTAL);

    prep_weights_kernel<<<640, 256>>>(W1, W2, W3);
    precompute_mma_kernel<<<dim3(10, 2), 256, PRE_SMEM_TOTAL>>>(qf, sf, b1);
    relation_mma_kernel<<<dim3(NS, NQ / TM), 256, SMEM_TOTAL>>>(b2, b3, W4, b4, out);
}

// round 11
// speedup vs baseline: 1.2202x; 1.2202x over previous
#include <cuda_runtime.h>
#include <cuda_fp16.h>
#include <math.h>
#include <stdint.h>

#define NQ 1024
#define NS 256
#define E  256
#define H1 256
#define H2 128
#define H3 64
#define TM 128          // query rows per CTA

// ---------------- warp-MMA helpers (plain sm_80+ PTX) -----------------------
__device__ __forceinline__ uint32_t smem_to_u32(const void* p) {
    uint32_t a;
    asm("{ .reg .u64 t; cvta.to.shared.u64 t, %1; cvt.u32.u64 %0, t; }" : "=r"(a) : "l"(p));
    return a;
}
__device__ __forceinline__ void ldsm4(uint32_t* r, uint32_t addr) {
    asm volatile("ldmatrix.sync.aligned.m8n8.x4.shared.b16 {%0,%1,%2,%3}, [%4];"
                 : "=r"(r[0]), "=r"(r[1]), "=r"(r[2]), "=r"(r[3]) : "r"(addr));
}
__device__ __forceinline__ void mma_f16(float* d, const uint32_t* a, const uint32_t* b) {
    asm volatile("mma.sync.aligned.m16n8k16.row.col.f32.f16.f16.f32 "
                 "{%0,%1,%2,%3}, {%4,%5,%6,%7}, {%8,%9}, {%0,%1,%2,%3};"
                 : "+f"(d[0]), "+f"(d[1]), "+f"(d[2]), "+f"(d[3])
                 : "r"(a[0]), "r"(a[1]), "r"(a[2]), "r"(a[3]), "r"(b[0]), "r"(b[1]));
}
__device__ __forceinline__ void cp_async16(uint32_t dst_smem, const void* src) {
    asm volatile("cp.async.cg.shared.global [%0], [%1], 16;"
                 :: "r"(dst_smem), "l"(src));
}
#define CP_ASYNC_COMMIT() asm volatile("cp.async.commit_group;" ::: "memory")
#define CP_ASYNC_WAIT0()  asm volatile("cp.async.wait_group 0;" ::: "memory")

__device__ __forceinline__ void split_f16(float x, __half& hi, __half& lo) {
    hi = __float2half_rn(x);
    lo = __float2half_rn(x - __half2float(hi));
}
__device__ __forceinline__ uint32_t pack2h(__half a, __half b) {
    __half2 t; t.x = a; t.y = b;
    return *reinterpret_cast<uint32_t*>(&t);
}
__device__ __forceinline__ uint32_t hadd2_relu(uint32_t a, uint32_t b) {
    __half2 r = __hmax2(__hadd2(*reinterpret_cast<__half2*>(&a),
                                *reinterpret_cast<__half2*>(&b)),
                        __half2(__half(0.0f), __half(0.0f)));
    return *reinterpret_cast<uint32_t*>(&r);
}
__device__ __forceinline__ float frelu(float x) { return fmaxf(x, 0.0f); }

// ---------------- global scratch (static) -----------------------------------
__device__ uint4  g_QpF[16 * 64 * 32];        // [K16][M16][lane] fp16 A-fragments
__device__ float  g_Sp [NS * H1];             // [s][k] (+b1)
__device__ __half g_W1TB_hi[163840];          // [(half*8+c)*256+n]*40+kk (kk<32)
__device__ __half g_W1TB_lo[163840];
__device__ __half g_W2TB[128 * 264];          // [n][264k] fp16, k<256 data
__device__ __half g_W3TB[8704];               // [n*136+k] fp16

// ---------------- main-kernel smem layout (bytes) ----------------------------
#define SM_W2   0         // whole W2^T [128n][264k] fp16 = 67584
#define SM_W3   0         // phase B: W3^T [64n][136k] = 17408 (aliases SM_W2)
#define SM_H2   67584     // h2 fp16 [128m][136k] = 34816 (ends 102400)
#define SM_SP16 102400    // 256 fp16 = 512
#define SM_B2S  102912    // 128 f32
#define SM_B3S  103424    // 64 f32
#define SM_W4S  103680    // 64 f32
#define SM_RED  103936    // 2*128 f32 = 1024
#define SMEM_TOTAL 104960

// ---------------- precompute-kernel smem layout ------------------------------
#define PSM_A  0          // feat fp16 [128m][264k] = 67584
#define PSM_B  67584      // W1 stage: 2 x (hi 10240 + lo 10240) = 40960
#define PB_STRIDE 20480
#define PRE_SMEM_TOTAL 108544

// ---------------------------------------------------------------------------
// Weight prep: W1 only (fp16 hi/lo transposed+padded), 4-way ILP grid-stride.
// W2/W3 conversion lives in the precompute launch (extra CTAs, concurrent).
// ---------------------------------------------------------------------------
__global__ void prep_w1_kernel(const float* __restrict__ W1)
{
    const int t0 = blockIdx.x * blockDim.x + threadIdx.x;   // 160*256 = 40960
    #pragma unroll
    for (int i = 0; i < 4; ++i) {
        const int t = t0 + i * 40960;
        const int kk = t % 40;
        const int n  = (t / 40) & 255;
        const int c  = (t / (40 * 256)) & 7;
        const int hf = t / (40 * 256 * 8);
        const float w = (kk < 32) ? W1[(hf * 256 + c * 32 + kk) * H1 + n] : 0.0f;
        __half hi, lo; split_f16(w, hi, lo);
        g_W1TB_hi[t] = hi;
        g_W1TB_lo[t] = lo;
    }
}

// ---------------------------------------------------------------------------
// Precompute via mma (f32 acc, W1 hi+lo): Qp -> g_QpF fragments; Sp -> g_Sp.
// mb 0..9: GEMM CTAs. mb 10..14: W2/W3 fp16 conversion (runs concurrently).
// ---------------------------------------------------------------------------
__global__ void __launch_bounds__(256)
precompute_mma_kernel(const float* __restrict__ qf,
                      const float* __restrict__ sf,
                      const float* __restrict__ b1,
                      const float* __restrict__ W2,
                      const float* __restrict__ W3)
{
    const int mb = blockIdx.x;         // 0..14
    const int nb = blockIdx.y;         // 0..1

    if (mb >= 10) {
        // ---- conversion CTAs: W2 -> g_W2TB, W3 -> g_W3TB ----
        const int cid = (mb - 10) * 2 + nb;     // 0..9
        for (int e = cid * 256 + threadIdx.x; e < 33792 + 8704; e += 2560) {
            if (e < 33792) {
                const int n = e / 264, k = e % 264;
                const float w = (k < 256) ? W2[k * H2 + n] : 0.0f;
                g_W2TB[e] = __float2half_rn(w);
            } else {
                const int t = e - 33792;
                const int n = t / 136, k = t % 136;
                const float w = (k < 128) ? W3[k * H3 + n] : 0.0f;
                g_W3TB[t] = __float2half_rn(w);
            }
        }
        return;
    }

    extern __shared__ char smem[];
    const uint32_t sb = smem_to_u32(smem);
    const int tid  = threadIdx.x;
    const int lane = tid & 31;
    const int wid  = tid >> 5;
    const int wm   = wid & 3;
    const int wn   = wid >> 2;
    const bool isQ = (mb < 8);
    const float* feat = isQ ? (qf + mb * 128 * E) : (sf + (mb - 8) * 128 * E);
    const int hf = isQ ? 0 : 1;

    {
        const int row = tid >> 1, hv = tid & 1;
        const float4* src = reinterpret_cast<const float4*>(feat + row * E);
        uint32_t* dst = reinterpret_cast<uint32_t*>(smem + PSM_A);
        #pragma unroll 8
        for (int j = 0; j < 32; ++j) {
            const float4 v = src[hv * 32 + j];
            const int u = row * 132 + (hv * 32 + j) * 2;
            dst[u]     = pack2h(__float2half_rn(v.x), __float2half_rn(v.y));
            dst[u + 1] = pack2h(__float2half_rn(v.z), __float2half_rn(v.w));
        }
    }
    {
        const char* srcH = (const char*)&g_W1TB_hi[((hf * 8 + 0) * 256 + nb * 128) * 40];
        const char* srcL = (const char*)&g_W1TB_lo[((hf * 8 + 0) * 256 + nb * 128) * 40];
        const uint32_t dstH = sb + PSM_B;
        #pragma unroll
        for (int i = 0; i < 3; ++i) {
            const int t = tid + 256 * i;
            if (t < 640) {
                cp_async16(dstH + t * 16, srcH + t * 16);
                cp_async16(dstH + 10240 + t * 16, srcL + t * 16);
            }
        }
        CP_ASYNC_COMMIT();
    }
    __syncthreads();

    float acc[2][8][4];
    #pragma unroll
    for (int a = 0; a < 2; a++)
        #pragma unroll
        for (int b = 0; b < 8; b++)
            #pragma unroll
            for (int c = 0; c < 4; c++) acc[a][b][c] = 0.0f;

    for (int c = 0; c < 8; ++c) {
        const int st = c & 1;
        CP_ASYNC_WAIT0();
        __syncthreads();
        if (c < 7) {
            const int base = ((hf * 8 + c + 1) * 256 + nb * 128) * 40;
            const char* srcH = (const char*)&g_W1TB_hi[base];
            const char* srcL = (const char*)&g_W1TB_lo[base];
            const uint32_t dstH = sb + PSM_B + (st ^ 1) * PB_STRIDE;
            #pragma unroll
            for (int i = 0; i < 3; ++i) {
                const int t = tid + 256 * i;
                if (t < 640) {
                    cp_async16(dstH + t * 16, srcH + t * 16);
                    cp_async16(dstH + 10240 + t * 16, srcL + t * 16);
                }
            }
            CP_ASYNC_COMMIT();
        }
        const uint32_t bufH = sb + PSM_B + st * PB_STRIDE;
        #pragma unroll
        for (int ks = 0; ks < 2; ++ks) {
            uint32_t afr[2][4];
            #pragma unroll
            for (int tm = 0; tm < 2; ++tm) {
                const int mrow = wm * 32 + tm * 16 + (lane & 7) + 8 * ((lane >> 3) & 1);
                const int kcol = c * 32 + ks * 16 + 8 * (lane >> 4);
                ldsm4(afr[tm], sb + PSM_A + mrow * 528 + kcol * 2);
            }
            #pragma unroll
            for (int tp = 0; tp < 4; ++tp) {
                uint32_t bh[4], bl[4];
                const int nrow = wn * 64 + tp * 16 + (lane & 7) + 8 * (lane >> 4);
                const int kcol = ks * 16 + 8 * ((lane >> 3) & 1);
                const uint32_t baddr = bufH + nrow * 80 + kcol * 2;
                ldsm4(bh, baddr);
                ldsm4(bl, baddr + 10240);
                #pragma unroll
                for (int tm = 0; tm < 2; ++tm) {
                    mma_f16(acc[tm][2*tp    ], afr[tm], &bh[0]);
                    mma_f16(acc[tm][2*tp    ], afr[tm], &bl[0]);
                    mma_f16(acc[tm][2*tp + 1], afr[tm], &bh[2]);
                    mma_f16(acc[tm][2*tp + 1], afr[tm], &bl[2]);
                }
            }
        }
    }

    if (isQ) {
        #pragma unroll
        for (int tm = 0; tm < 2; ++tm)
            #pragma unroll
            for (int tnp = 0; tnp < 4; ++tnp) {
                const int K16 = nb * 8 + wn * 4 + tnp;
                const int M16 = mb * 8 + wm * 2 + tm;
                uint4 v;
                v.x = pack2h(__float2half_rn(acc[tm][2*tnp][0]),
                             __float2half_rn(acc[tm][2*tnp][1]));
                v.y = pack2h(__float2half_rn(acc[tm][2*tnp][2]),
                             __float2half_rn(acc[tm][2*tnp][3]));
                v.z = pack2h(__float2half_rn(acc[tm][2*tnp+1][0]),
                             __float2half_rn(acc[tm][2*tnp+1][1]));
                v.w = pack2h(__float2half_rn(acc[tm][2*tnp+1][2]),
                             __float2half_rn(acc[tm][2*tnp+1][3]));
                g_QpF[(K16 * 64 + M16) * 32 + lane] = v;
            }
    } else {
        const int s0 = (mb - 8) * 128;
        #pragma unroll
        for (int tm = 0; tm < 2; ++tm)
            #pragma unroll
            for (int tn = 0; tn < 8; ++tn) {
                const int n = nb * 128 + wn * 64 + tn * 8 + (lane & 3) * 2;
                const float bb0 = b1[n], bb1 = b1[n + 1];
                #pragma unroll
                for (int rr = 0; rr < 2; ++rr) {
                    const int m = wm * 32 + tm * 16 + rr * 8 + (lane >> 2);
                    g_Sp[(s0 + m) * H1 + n]     = acc[tm][tn][2*rr]     + bb0;
                    g_Sp[(s0 + m) * H1 + n + 1] = acc[tm][tn][2*rr + 1] + bb1;
                }
            }
    }
}

// ---------------------------------------------------------------------------
// Fused MLP (R9 winner, f32 accumulators): whole W2 resident; barrier-free
// layer2 mainloop; register-fragment A (relu(Qp+Sp) via HADD2/HMAX2).
// ---------------------------------------------------------------------------
__global__ void __launch_bounds__(256, 2)
relation_mma_kernel(const float* __restrict__ b2,
                    const float* __restrict__ b3,
                    const float* __restrict__ W4,
                    const float* __restrict__ b4,
                    float* __restrict__ out)
{
    extern __shared__ char smem[];
    const uint32_t sb = smem_to_u32(smem);
    const int tid  = threadIdx.x;
    const int lane = tid & 31;
    const int wid  = tid >> 5;
    const int wm   = wid & 3;
    const int wn   = wid >> 2;
    const int s_idx = blockIdx.x;
    const int q0    = blockIdx.y * TM;
    const int M16b  = blockIdx.y * 8 + wm * 2;

    float* b2s = (float*)(smem + SM_B2S);
    float* b3s = (float*)(smem + SM_B3S);
    float* W4s = (float*)(smem + SM_W4S);
    float* red = (float*)(smem + SM_RED);
    __half* sp16 = (__half*)(smem + SM_SP16);

    sp16[tid] = __float2half_rn(g_Sp[s_idx * H1 + tid]);
    if (tid < H2) b2s[tid] = b2[tid];
    if (tid < H3) { b3s[tid] = b3[tid]; W4s[tid] = W4[tid]; }

    // ---- prologue: cp.async the WHOLE W2 (67584 B = 4224 x 16B) ----
    {
        const char* src = (const char*)g_W2TB;
        #pragma unroll
        for (int i = 0; i < 17; ++i) {
            const int t = tid + 256 * i;
            if (t < 4224) cp_async16(sb + SM_W2 + t * 16, src + t * 16);
        }
        CP_ASYNC_COMMIT();
    }
    uint4 aq[2][2];
    #pragma unroll
    for (int tm = 0; tm < 2; ++tm)
        #pragma unroll
        for (int ks = 0; ks < 2; ++ks)
            aq[tm][ks] = g_QpF[(ks * 64 + M16b + tm) * 32 + lane];

    float acc[2][8][4];
    #pragma unroll
    for (int a = 0; a < 2; a++)
        #pragma unroll
        for (int b = 0; b < 8; b++)
            #pragma unroll
            for (int c = 0; c < 4; c++) acc[a][b][c] = 0.0f;

    CP_ASYNC_WAIT0();
    __syncthreads();   // W2 + sp16 + biases visible; only barrier before loop

    // ============ layer2 mainloop: 8 chunks of k=32, barrier-free ===========
    #pragma unroll
    for (int c = 0; c < 8; ++c) {
        uint32_t af[2][2][4];
        #pragma unroll
        for (int ks = 0; ks < 2; ++ks) {
            const uint32_t spA = *(const uint32_t*)(smem + SM_SP16 + c * 64 + ks * 32 + (lane & 3) * 4);
            const uint32_t spB = *(const uint32_t*)(smem + SM_SP16 + c * 64 + ks * 32 + (lane & 3) * 4 + 16);
            #pragma unroll
            for (int tm = 0; tm < 2; ++tm) {
                af[tm][ks][0] = hadd2_relu(aq[tm][ks].x, spA);
                af[tm][ks][1] = hadd2_relu(aq[tm][ks].y, spA);
                af[tm][ks][2] = hadd2_relu(aq[tm][ks].z, spB);
                af[tm][ks][3] = hadd2_relu(aq[tm][ks].w, spB);
            }
        }
        if (c < 7) {
            #pragma unroll
            for (int tm = 0; tm < 2; ++tm)
                #pragma unroll
                for (int ks = 0; ks < 2; ++ks)
                    aq[tm][ks] = g_QpF[(((c + 1) * 2 + ks) * 64 + M16b + tm) * 32 + lane];
        }
        #pragma unroll
        for (int ks = 0; ks < 2; ++ks) {
            #pragma unroll
            for (int tp = 0; tp < 4; ++tp) {
                uint32_t bh[4];
                const int nrow = wn * 64 + tp * 16 + (lane & 7) + 8 * (lane >> 4);
                const int kcol = c * 32 + ks * 16 + 8 * ((lane >> 3) & 1);
                ldsm4(bh, sb + SM_W2 + nrow * 528 + kcol * 2);
                #pragma unroll
                for (int tm = 0; tm < 2; ++tm) {
                    mma_f16(acc[tm][2*tp    ], af[tm][ks], &bh[0]);
                    mma_f16(acc[tm][2*tp + 1], af[tm][ks], &bh[2]);
                }
            }
        }
    }
    __syncthreads();   // all W2 reads done CTA-wide; W2 region reusable

    // stage W3^T into W2's region via cp.async (overlaps epilogue below)
    {
        const char* srcH = (const char*)g_W3TB;
        #pragma unroll
        for (int i = 0; i < 5; ++i) {
            const int t = tid + 256 * i;
            if (t < 1088) cp_async16(sb + SM_W3 + t * 16, srcH + t * 16);
        }
        CP_ASYNC_COMMIT();
    }
    // layer2 epilogue: bias+relu -> fp16 -> h2[m][k]
    {
        uint32_t* hh = reinterpret_cast<uint32_t*>(smem + SM_H2);
        #pragma unroll
        for (int tm = 0; tm < 2; ++tm) {
            #pragma unroll
            for (int tn = 0; tn < 8; ++tn) {
                const int n = wn * 64 + tn * 8 + (lane & 3) * 2;
                const int m = wm * 32 + tm * 16 + (lane >> 2);
                const float bn0 = b2s[n], bn1 = b2s[n + 1];
                #pragma unroll
                for (int rr = 0; rr < 2; ++rr) {
                    const float x0 = frelu(acc[tm][tn][2*rr    ] + bn0);
                    const float x1 = frelu(acc[tm][tn][2*rr + 1] + bn1);
                    hh[(m + 8*rr) * 68 + (n >> 1)] =
                        pack2h(__float2half_rn(x0), __float2half_rn(x1));
                }
            }
        }
    }
    CP_ASYNC_WAIT0();
    __syncthreads();

    // =================== layer3: h2[128x128] @ W3[128x64] ===================
    float acc3[2][4][4];
    #pragma unroll
    for (int a = 0; a < 2; a++)
        #pragma unroll
        for (int b = 0; b < 4; b++)
            #pragma unroll
            for (int c = 0; c < 4; c++) acc3[a][b][c] = 0.0f;

    #pragma unroll
    for (int ks = 0; ks < 8; ++ks) {
        uint32_t afr[2][4];
        #pragma unroll
        for (int tm = 0; tm < 2; ++tm) {
            const int mrow = wm * 32 + tm * 16 + (lane & 7) + 8 * ((lane >> 3) & 1);
            const int kcol = ks * 16 + 8 * (lane >> 4);
            ldsm4(afr[tm], sb + SM_H2 + mrow * 272 + kcol * 2);
        }
        #pragma unroll
        for (int tp = 0; tp < 2; ++tp) {
            uint32_t bh[4];
            const int nrow = wn * 32 + tp * 16 + (lane & 7) + 8 * (lane >> 4);
            const int kcol = ks * 16 + 8 * ((lane >> 3) & 1);
            ldsm4(bh, sb + SM_W3 + nrow * 272 + kcol * 2);
            #pragma unroll
            for (int tm = 0; tm < 2; ++tm) {
                mma_f16(acc3[tm][2*tp    ], afr[tm], &bh[0]);
                mma_f16(acc3[tm][2*tp + 1], afr[tm], &bh[2]);
            }
        }
    }

    // ============== layer3 epilogue + layer4 (registers + shfl) =============
    float part[4] = {0.0f, 0.0f, 0.0f, 0.0f};
    #pragma unroll
    for (int tn = 0; tn < 4; ++tn) {
        const int n = wn * 32 + tn * 8 + (lane & 3) * 2;
        const float bn0 = b3s[n], bn1 = b3s[n + 1];
        const float w0 = W4s[n],  w1 = W4s[n + 1];
        #pragma unroll
        for (int tm = 0; tm < 2; ++tm) {
            #pragma unroll
            for (int rr = 0; rr < 2; ++rr) {
                part[tm*2 + rr] += frelu(acc3[tm][tn][2*rr    ] + bn0) * w0
                                 + frelu(acc3[tm][tn][2*rr + 1] + bn1) * w1;
            }
        }
    }
    #pragma unroll
    for (int i = 0; i < 4; ++i) {
        part[i] += __shfl_xor_sync(0xffffffffu, part[i], 1);
        part[i] += __shfl_xor_sync(0xffffffffu, part[i], 2);
    }
    if ((lane & 3) == 0) {
        #pragma unroll
        for (int tm = 0; tm < 2; ++tm)
            #pragma unroll
            for (int rr = 0; rr < 2; ++rr) {
                const int m = wm * 32 + tm * 16 + rr * 8 + (lane >> 2);
                red[wn * 128 + m] = part[tm*2 + rr];
            }
    }
    __syncthreads();
    if (tid < 128) {
        const float v = red[tid] + red[128 + tid] + b4[0];
        out[(q0 + tid) * NS + s_idx] = 1.0f / (1.0f + expf(-v));
    }
}

// ---------------------------------------------------------------------------
extern "C" void kernel_launch(void* const* d_in, const int* in_sizes, int n_in,
                              void* d_out, int out_size)
{
    const float* qf = (const float*)d_in[0];
    const float* sf = (const float*)d_in[1];
    // d_in[2] = support_y (unused)
    const float* W1 = (const float*)d_in[3];
    const float* b1 = (const float*)d_in[4];
    const float* W2 = (const float*)d_in[5];
    const float* b2 = (const float*)d_in[6];
    const float* W3 = (const float*)d_in[7];
    const float* b3 = (const float*)d_in[8];
    const float* W4 = (const float*)d_in[9];
    const float* b4 = (const float*)d_in[10];
    float* out = (float*)d_out;

    cudaFuncSetAttribute(relation_mma_kernel,
                         cudaFuncAttributeMaxDynamicSharedMemorySize, SMEM_TOTAL);
    cudaFuncSetAttribute(precompute_mma_kernel,
                         cudaFuncAttributeMaxDynamicSharedMemorySize, PRE_SMEM_TOTAL);

    prep_w1_kernel<<<160, 256>>>(W1);
    precompute_mma_kernel<<<dim3(15, 2), 256, PRE_SMEM_TOTAL>>>(qf, sf, b1, W2, W3);
    relation_mma_kernel<<<dim3(NS, NQ / TM), 256, SMEM_TOTAL>>>(b2, b3, W4, b4, out);
}